// round 2
// baseline (speedup 1.0000x reference)
#include <cuda_runtime.h>

#define NN   100000
#define EE   1600000
#define ET   (EE + NN)          // edges + self loops = 1,700,000
#define HID  128
#define NT   32                 // nodes per block in per-node kernels
#define KC   96                 // K-chunk for 768-wide MLPs

// ---------------- scratch (device globals: no allocation allowed) -------------
__device__ __align__(16) float g_xw1 [(size_t)NN * HID];
__device__ __align__(16) float g_es1 [NN * 4];
__device__ __align__(16) float g_ed1 [NN * 4];
__device__ __align__(16) float g_den1[NN * 4];
__device__ __align__(16) float g_ex1 [(size_t)ET * 4];
__device__ __align__(16) float g_out1[(size_t)NN * HID];
__device__ __align__(16) float g_xw2 [(size_t)NN * HID];
__device__ __align__(16) float g_es2 [NN];
__device__ __align__(16) float g_ed2 [NN];
__device__ __align__(16) float g_den2[NN];
__device__ __align__(16) float g_ex2 [ET];
__device__ __align__(16) float g_out2[(size_t)NN * HID];

__device__ __forceinline__ float lrelu01(float v) { return v > 0.f ? v : 0.01f * v; }
__device__ __forceinline__ float lrelu2 (float v) { return v > 0.f ? v : 0.2f  * v; }

// ---------------- zero accumulators (replayed every launch) ------------------
__global__ void k_zero() {
    size_t i = (size_t)blockIdx.x * blockDim.x + threadIdx.x;
    if (i < (size_t)NN * HID) { g_out1[i] = 0.f; g_out2[i] = 0.f; }
    if (i < (size_t)NN * 4)   g_den1[i] = 0.f;
    if (i < (size_t)NN)       g_den2[i] = 0.f;
}

// ---------------- features -> x -> Wi -> g1 projection + attn logits ---------
__global__ void __launch_bounds__(128, 1) k_features(
    const float* __restrict__ des, const float* __restrict__ twt,
    const float* __restrict__ npr, const float* __restrict__ cpr,
    const float* __restrict__ Wd, const float* __restrict__ bd,
    const float* __restrict__ Wt, const float* __restrict__ bt,
    const float* __restrict__ Wn, const float* __restrict__ bn,
    const float* __restrict__ Wc, const float* __restrict__ bc,
    const float* __restrict__ Wi, const float* __restrict__ bi,
    const float* __restrict__ g1W, const float* __restrict__ g1as,
    const float* __restrict__ g1ad)
{
    __shared__ float sh[NT * 132];          // node activations, stride 132 (pad)
    __shared__ float sbuf[2 * NT * KC];     // stage1: des/tweet tiles; later: x2 rows

    const int tid = threadIdx.x;
    const int n0  = blockIdx.x * NT;
    const int j   = tid;

    float acc[NT];
#pragma unroll
    for (int m = 0; m < NT; m++) acc[m] = 0.f;

    // ---- stage 1: des (warp0) / tweet (warp1), K-chunked -------------------
    for (int c = 0; c < 768 / KC; c++) {
        const int kb = c * KC;
        for (int idx = tid; idx < NT * KC; idx += 128) {
            const int r = idx / KC, col = idx - r * KC;
            sbuf[idx]           = des[(size_t)(n0 + r) * 768 + kb + col];
            sbuf[NT * KC + idx] = twt[(size_t)(n0 + r) * 768 + kb + col];
        }
        __syncthreads();
        if (j < 64) {
            const float* w = (j < 32 ? Wd + (size_t)j * 768
                                     : Wt + (size_t)(j - 32) * 768) + kb;
            const float* s = (j < 32 ? sbuf : sbuf + NT * KC);
            for (int k = 0; k < KC; k += 8) {
                const float4 w0 = *(const float4*)(w + k);
                const float4 w1 = *(const float4*)(w + k + 4);
#pragma unroll
                for (int m = 0; m < NT; m++) {
                    const float4 a0 = *(const float4*)(s + m * KC + k);
                    const float4 a1 = *(const float4*)(s + m * KC + k + 4);
                    acc[m] += a0.x * w0.x + a0.y * w0.y + a0.z * w0.z + a0.w * w0.w;
                    acc[m] += a1.x * w1.x + a1.y * w1.y + a1.z * w1.z + a1.w * w1.w;
                }
            }
        }
        __syncthreads();
    }

    // ---- stage 1 epilogue: write x = concat(d,t,n,c) rows ------------------
    if (j < 32) {
        const float b = bd[j];
#pragma unroll
        for (int m = 0; m < NT; m++) sh[m * 132 + j] = lrelu01(acc[m] + b);
    } else if (j < 64) {
        const float b = bt[j - 32];
#pragma unroll
        for (int m = 0; m < NT; m++) sh[m * 132 + j] = lrelu01(acc[m] + b);
    } else if (j < 96) {
        const int jj = j - 64;
        const float w0 = Wn[jj * 5], w1 = Wn[jj * 5 + 1], w2 = Wn[jj * 5 + 2],
                    w3 = Wn[jj * 5 + 3], w4 = Wn[jj * 5 + 4];
        const float b = bn[jj];
        for (int m = 0; m < NT; m++) {
            const float* r = npr + (size_t)(n0 + m) * 5;
            sh[m * 132 + j] =
                lrelu01(r[0] * w0 + r[1] * w1 + r[2] * w2 + r[3] * w3 + r[4] * w4 + b);
        }
    } else {
        const int jj = j - 96;
        const float w0 = Wc[jj * 3], w1 = Wc[jj * 3 + 1], w2 = Wc[jj * 3 + 2];
        const float b = bc[jj];
        for (int m = 0; m < NT; m++) {
            const float* r = cpr + (size_t)(n0 + m) * 3;
            sh[m * 132 + j] = lrelu01(r[0] * w0 + r[1] * w1 + r[2] * w2 + b);
        }
    }
    __syncthreads();

    // ---- stage 2: x2 = lrelu(x @ Wi^T + bi) --------------------------------
    {
        const float* w = Wi + (size_t)j * HID;
#pragma unroll
        for (int m = 0; m < NT; m++) acc[m] = 0.f;
        for (int k = 0; k < HID; k += 8) {
            const float4 w0 = *(const float4*)(w + k);
            const float4 w1 = *(const float4*)(w + k + 4);
#pragma unroll
            for (int m = 0; m < NT; m++) {
                const float4 a0 = *(const float4*)(sh + m * 132 + k);
                const float4 a1 = *(const float4*)(sh + m * 132 + k + 4);
                acc[m] += a0.x * w0.x + a0.y * w0.y + a0.z * w0.z + a0.w * w0.w;
                acc[m] += a1.x * w1.x + a1.y * w1.y + a1.z * w1.z + a1.w * w1.w;
            }
        }
        const float b = bi[j];
#pragma unroll
        for (int m = 0; m < NT; m++) sbuf[m * 132 + j] = lrelu01(acc[m] + b);
    }
    __syncthreads();

    // ---- stage 3: xw1 = x2 @ g1_W^T ; e_src/e_dst via warp reduce ----------
    {
        const float* w = g1W + (size_t)j * HID;
#pragma unroll
        for (int m = 0; m < NT; m++) acc[m] = 0.f;
        for (int k = 0; k < HID; k += 8) {
            const float4 w0 = *(const float4*)(w + k);
            const float4 w1 = *(const float4*)(w + k + 4);
#pragma unroll
            for (int m = 0; m < NT; m++) {
                const float4 a0 = *(const float4*)(sbuf + m * 132 + k);
                const float4 a1 = *(const float4*)(sbuf + m * 132 + k + 4);
                acc[m] += a0.x * w0.x + a0.y * w0.y + a0.z * w0.z + a0.w * w0.w;
                acc[m] += a1.x * w1.x + a1.y * w1.y + a1.z * w1.z + a1.w * w1.w;
            }
        }
#pragma unroll
        for (int m = 0; m < NT; m++) g_xw1[(size_t)(n0 + m) * HID + j] = acc[m];

        const float aj = g1as[j], dj = g1ad[j];
        const int h = j >> 5, lane = j & 31;   // warp == head for GAT1
#pragma unroll
        for (int m = 0; m < NT; m++) {
            float vs = acc[m] * aj, vd = acc[m] * dj;
#pragma unroll
            for (int o = 16; o > 0; o >>= 1) {
                vs += __shfl_xor_sync(0xffffffffu, vs, o);
                vd += __shfl_xor_sync(0xffffffffu, vd, o);
            }
            if (lane == 0) {
                g_es1[(n0 + m) * 4 + h] = vs;
                g_ed1[(n0 + m) * 4 + h] = vd;
            }
        }
    }
}

// ---------------- GAT1 edge pass: exp + denominator ---------------------------
__global__ void k_gat1_edge(const int* __restrict__ ei) {
    const int i = blockIdx.x * blockDim.x + threadIdx.x;
    if (i >= ET) return;
    int src, dst;
    if (i < EE) { src = ei[i]; dst = ei[EE + i]; }
    else        { src = dst = i - EE; }
    const float4 es = *(const float4*)(g_es1 + src * 4);
    const float4 ed = *(const float4*)(g_ed1 + dst * 4);
    float4 ex;
    ex.x = expf(lrelu2(es.x + ed.x));
    ex.y = expf(lrelu2(es.y + ed.y));
    ex.z = expf(lrelu2(es.z + ed.z));
    ex.w = expf(lrelu2(es.w + ed.w));
    *(float4*)(g_ex1 + (size_t)i * 4) = ex;
    atomicAdd(&g_den1[dst * 4 + 0], ex.x);
    atomicAdd(&g_den1[dst * 4 + 1], ex.y);
    atomicAdd(&g_den1[dst * 4 + 2], ex.z);
    atomicAdd(&g_den1[dst * 4 + 3], ex.w);
}

// ---------------- GAT1 aggregation: warp per edge -----------------------------
__global__ void k_gat1_agg(const int* __restrict__ ei) {
    const int gw = (blockIdx.x * blockDim.x + threadIdx.x) >> 5;
    const int lane = threadIdx.x & 31;
    if (gw >= ET) return;
    int src, dst;
    if (gw < EE) { src = ei[gw]; dst = ei[EE + gw]; }
    else         { src = dst = gw - EE; }
    const float4 ex = *(const float4*)(g_ex1 + (size_t)gw * 4);
    const float4 dn = *(const float4*)(g_den1 + dst * 4);
    const float a0 = ex.x / dn.x, a1 = ex.y / dn.y, a2 = ex.z / dn.z, a3 = ex.w / dn.w;
    const float* xs = g_xw1 + (size_t)src * HID;
    float*       od = g_out1 + (size_t)dst * HID;
    atomicAdd(od + lane,       xs[lane]       * a0);
    atomicAdd(od + 32 + lane,  xs[32 + lane]  * a1);
    atomicAdd(od + 64 + lane,  xs[64 + lane]  * a2);
    atomicAdd(od + 96 + lane,  xs[96 + lane]  * a3);
}

// ---------------- GAT2 projection + attn logits -------------------------------
__global__ void __launch_bounds__(128, 1) k_gat2_prep(
    const float* __restrict__ g1b, const float* __restrict__ g2W,
    const float* __restrict__ g2as, const float* __restrict__ g2ad)
{
    __shared__ float sx[NT * 132];
    __shared__ float sp[2][4][NT];
    const int tid = threadIdx.x, n0 = blockIdx.x * NT, j = tid;

    for (int idx = tid; idx < NT * HID; idx += 128) {
        const int m = idx >> 7, c = idx & 127;
        sx[m * 132 + c] = g_out1[(size_t)(n0 + m) * HID + c] + g1b[c];
    }
    __syncthreads();

    float acc[NT];
#pragma unroll
    for (int m = 0; m < NT; m++) acc[m] = 0.f;
    const float* w = g2W + (size_t)j * HID;
    for (int k = 0; k < HID; k += 8) {
        const float4 w0 = *(const float4*)(w + k);
        const float4 w1 = *(const float4*)(w + k + 4);
#pragma unroll
        for (int m = 0; m < NT; m++) {
            const float4 a0 = *(const float4*)(sx + m * 132 + k);
            const float4 a1 = *(const float4*)(sx + m * 132 + k + 4);
            acc[m] += a0.x * w0.x + a0.y * w0.y + a0.z * w0.z + a0.w * w0.w;
            acc[m] += a1.x * w1.x + a1.y * w1.y + a1.z * w1.z + a1.w * w1.w;
        }
    }
#pragma unroll
    for (int m = 0; m < NT; m++) g_xw2[(size_t)(n0 + m) * HID + j] = acc[m];

    const float aj = g2as[j], dj = g2ad[j];
    const int wp = j >> 5, lane = j & 31;
#pragma unroll
    for (int m = 0; m < NT; m++) {
        float vs = acc[m] * aj, vd = acc[m] * dj;
#pragma unroll
        for (int o = 16; o > 0; o >>= 1) {
            vs += __shfl_xor_sync(0xffffffffu, vs, o);
            vd += __shfl_xor_sync(0xffffffffu, vd, o);
        }
        if (lane == 0) { sp[0][wp][m] = vs; sp[1][wp][m] = vd; }
    }
    __syncthreads();
    if (tid < 32) {
        g_es2[n0 + tid] = sp[0][0][tid] + sp[0][1][tid] + sp[0][2][tid] + sp[0][3][tid];
    } else if (tid < 64) {
        const int m = tid - 32;
        g_ed2[n0 + m] = sp[1][0][m] + sp[1][1][m] + sp[1][2][m] + sp[1][3][m];
    }
}

// ---------------- GAT2 edge passes -------------------------------------------
__global__ void k_gat2_edge(const int* __restrict__ ei) {
    const int i = blockIdx.x * blockDim.x + threadIdx.x;
    if (i >= ET) return;
    int src, dst;
    if (i < EE) { src = ei[i]; dst = ei[EE + i]; }
    else        { src = dst = i - EE; }
    const float ex = expf(lrelu2(g_es2[src] + g_ed2[dst]));
    g_ex2[i] = ex;
    atomicAdd(&g_den2[dst], ex);
}

__global__ void k_gat2_agg(const int* __restrict__ ei) {
    const int gw = (blockIdx.x * blockDim.x + threadIdx.x) >> 5;
    const int lane = threadIdx.x & 31;
    if (gw >= ET) return;
    int src, dst;
    if (gw < EE) { src = ei[gw]; dst = ei[EE + gw]; }
    else         { src = dst = gw - EE; }
    const float a = g_ex2[gw] / g_den2[dst];
    const float* xs = g_xw2 + (size_t)src * HID;
    float*       od = g_out2 + (size_t)dst * HID;
    atomicAdd(od + lane,      xs[lane]      * a);
    atomicAdd(od + 32 + lane, xs[32 + lane] * a);
    atomicAdd(od + 64 + lane, xs[64 + lane] * a);
    atomicAdd(od + 96 + lane, xs[96 + lane] * a);
}

// ---------------- output head ------------------------------------------------
__global__ void __launch_bounds__(128, 1) k_final(
    const float* __restrict__ g2b, const float* __restrict__ Wo1,
    const float* __restrict__ bo1, const float* __restrict__ Wo2,
    const float* __restrict__ bo2, float* __restrict__ out)
{
    __shared__ float sx[NT * 132];
    __shared__ float sp[2][4][NT];
    const int tid = threadIdx.x, n0 = blockIdx.x * NT, j = tid;

    for (int idx = tid; idx < NT * HID; idx += 128) {
        const int m = idx >> 7, c = idx & 127;
        sx[m * 132 + c] = g_out2[(size_t)(n0 + m) * HID + c] + g2b[c];
    }
    __syncthreads();

    float acc[NT];
#pragma unroll
    for (int m = 0; m < NT; m++) acc[m] = 0.f;
    const float* w = Wo1 + (size_t)j * HID;
    for (int k = 0; k < HID; k += 8) {
        const float4 w0 = *(const float4*)(w + k);
        const float4 w1 = *(const float4*)(w + k + 4);
#pragma unroll
        for (int m = 0; m < NT; m++) {
            const float4 a0 = *(const float4*)(sx + m * 132 + k);
            const float4 a1 = *(const float4*)(sx + m * 132 + k + 4);
            acc[m] += a0.x * w0.x + a0.y * w0.y + a0.z * w0.z + a0.w * w0.w;
            acc[m] += a1.x * w1.x + a1.y * w1.y + a1.z * w1.z + a1.w * w1.w;
        }
    }
    const float b1 = bo1[j];
    const float w0o = Wo2[j], w1o = Wo2[HID + j];
    const int wp = j >> 5, lane = j & 31;
#pragma unroll
    for (int m = 0; m < NT; m++) {
        const float y = lrelu01(acc[m] + b1);
        float v0 = y * w0o, v1 = y * w1o;
#pragma unroll
        for (int o = 16; o > 0; o >>= 1) {
            v0 += __shfl_xor_sync(0xffffffffu, v0, o);
            v1 += __shfl_xor_sync(0xffffffffu, v1, o);
        }
        if (lane == 0) { sp[0][wp][m] = v0; sp[1][wp][m] = v1; }
    }
    __syncthreads();
    if (tid < 32) {
        out[(size_t)(n0 + tid) * 2] =
            sp[0][0][tid] + sp[0][1][tid] + sp[0][2][tid] + sp[0][3][tid] + bo2[0];
    } else if (tid < 64) {
        const int m = tid - 32;
        out[(size_t)(n0 + m) * 2 + 1] =
            sp[1][0][m] + sp[1][1][m] + sp[1][2][m] + sp[1][3][m] + bo2[1];
    }
}

// ---------------- launch ------------------------------------------------------
extern "C" void kernel_launch(void* const* d_in, const int* in_sizes, int n_in,
                              void* d_out, int out_size) {
    const float* des  = (const float*)d_in[0];
    const float* twt  = (const float*)d_in[1];
    const float* npr  = (const float*)d_in[2];
    const float* cpr  = (const float*)d_in[3];
    const int*   ei   = (const int*)d_in[4];   // JAX x64 disabled -> int32
    const float* Wd = (const float*)d_in[5];   const float* bd = (const float*)d_in[6];
    const float* Wt = (const float*)d_in[7];   const float* bt = (const float*)d_in[8];
    const float* Wn = (const float*)d_in[9];   const float* bn = (const float*)d_in[10];
    const float* Wc = (const float*)d_in[11];  const float* bc = (const float*)d_in[12];
    const float* Wi = (const float*)d_in[13];  const float* bi = (const float*)d_in[14];
    const float* g1W  = (const float*)d_in[15];
    const float* g1as = (const float*)d_in[16];
    const float* g1ad = (const float*)d_in[17];
    const float* g1b  = (const float*)d_in[18];
    const float* g2W  = (const float*)d_in[19];
    const float* g2as = (const float*)d_in[20];
    const float* g2ad = (const float*)d_in[21];
    const float* g2b  = (const float*)d_in[22];
    const float* Wo1  = (const float*)d_in[23]; const float* bo1 = (const float*)d_in[24];
    const float* Wo2  = (const float*)d_in[25]; const float* bo2 = (const float*)d_in[26];
    float* out = (float*)d_out;

    k_zero<<<((size_t)NN * HID + 255) / 256, 256>>>();
    k_features<<<NN / NT, 128>>>(des, twt, npr, cpr, Wd, bd, Wt, bt, Wn, bn,
                                 Wc, bc, Wi, bi, g1W, g1as, g1ad);
    k_gat1_edge<<<(ET + 255) / 256, 256>>>(ei);
    k_gat1_agg<<<(ET + 7) / 8, 256>>>(ei);
    k_gat2_prep<<<NN / NT, 128>>>(g1b, g2W, g2as, g2ad);
    k_gat2_edge<<<(ET + 255) / 256, 256>>>(ei);
    k_gat2_agg<<<(ET + 7) / 8, 256>>>(ei);
    k_final<<<NN / NT, 128>>>(g2b, Wo1, bo1, Wo2, bo2, out);
}

// round 3
// speedup vs baseline: 1.3714x; 1.3714x over previous
#include <cuda_runtime.h>

#define NN   100000
#define EE   1600000
#define ET   (EE + NN)          // edges + self loops = 1,700,000
#define HID  128
#define NT   32                 // nodes per block in per-node kernels
#define KC   96                 // K-chunk for 768-wide MLPs

// ---------------- scratch (device globals: no allocation allowed) -------------
__device__ __align__(16) float g_xw1 [(size_t)NN * HID];
__device__ __align__(16) float g_es1 [NN * 4];
__device__ __align__(16) float g_ed1 [NN * 4];
__device__ __align__(16) float g_ex1 [(size_t)ET * 4];   // slot-indexed
__device__ __align__(16) float g_out1[(size_t)NN * HID];
__device__ __align__(16) float g_xw2 [(size_t)NN * HID];
__device__ __align__(16) float g_es2 [NN];
__device__ __align__(16) float g_ed2 [NN];
__device__ __align__(16) float g_ex2 [ET];               // slot-indexed
__device__ __align__(16) float g_out2[(size_t)NN * HID];

// CSR (dst-grouped), rebuilt every launch (graph-capture safe, no allocs)
__device__ int g_cnt[NN];
__device__ int g_rs [NN + 1];
__device__ int g_cur[NN];
__device__ int g_csrc[ET];
__device__ int g_cdst[ET];

__device__ __forceinline__ float lrelu01(float v) { return v > 0.f ? v : 0.01f * v; }
__device__ __forceinline__ float lrelu2 (float v) { return v > 0.f ? v : 0.2f  * v; }

// ---------------- CSR build ---------------------------------------------------
__global__ void k_init_cnt() {
    int i = blockIdx.x * blockDim.x + threadIdx.x;
    if (i < NN) g_cnt[i] = 1;            // self loop pre-counted
}

__global__ void k_count(const int* __restrict__ ei) {
    int i = blockIdx.x * blockDim.x + threadIdx.x;
    if (i < EE) atomicAdd(&g_cnt[ei[EE + i]], 1);
}

__global__ void __launch_bounds__(1024, 1) k_scan() {  // single block
    __shared__ int ssum[1024];
    const int t = threadIdx.x;
    const int C = (NN + 1023) / 1024;    // 98
    const int beg = t * C;
    const int end = (beg + C < NN) ? beg + C : NN;
    int s = 0;
    for (int i = beg; i < end; i++) s += g_cnt[i];
    ssum[t] = s;
    __syncthreads();
    for (int o = 1; o < 1024; o <<= 1) {
        int v = (t >= o) ? ssum[t - o] : 0;
        __syncthreads();
        ssum[t] += v;
        __syncthreads();
    }
    int pre = (t == 0) ? 0 : ssum[t - 1];
    for (int i = beg; i < end; i++) {
        g_rs[i] = pre;
        g_cur[i] = pre;
        pre += g_cnt[i];
    }
    if (t == 0) g_rs[NN] = ET;
}

__global__ void k_fill(const int* __restrict__ ei) {
    int i = blockIdx.x * blockDim.x + threadIdx.x;
    if (i >= ET) return;
    int src, dst;
    if (i < EE) { src = ei[i]; dst = ei[EE + i]; }
    else        { src = dst = i - EE; }
    const int slot = atomicAdd(&g_cur[dst], 1);
    g_csrc[slot] = src;
    g_cdst[slot] = dst;
}

// ---------------- features -> x -> Wi -> g1 projection + attn logits ---------
__global__ void __launch_bounds__(128, 1) k_features(
    const float* __restrict__ des, const float* __restrict__ twt,
    const float* __restrict__ npr, const float* __restrict__ cpr,
    const float* __restrict__ Wd, const float* __restrict__ bd,
    const float* __restrict__ Wt, const float* __restrict__ bt,
    const float* __restrict__ Wn, const float* __restrict__ bn,
    const float* __restrict__ Wc, const float* __restrict__ bc,
    const float* __restrict__ Wi, const float* __restrict__ bi,
    const float* __restrict__ g1W, const float* __restrict__ g1as,
    const float* __restrict__ g1ad)
{
    __shared__ float sh[NT * 132];          // node activations, stride 132 (pad)
    __shared__ float sbuf[2 * NT * KC];     // stage1: des/tweet tiles; later: x2 rows

    const int tid = threadIdx.x;
    const int n0  = blockIdx.x * NT;
    const int j   = tid;

    float acc[NT];
#pragma unroll
    for (int m = 0; m < NT; m++) acc[m] = 0.f;

    // ---- stage 1: des (warp0) / tweet (warp1), K-chunked -------------------
    for (int c = 0; c < 768 / KC; c++) {
        const int kb = c * KC;
        for (int idx = tid; idx < NT * KC; idx += 128) {
            const int r = idx / KC, col = idx - r * KC;
            sbuf[idx]           = des[(size_t)(n0 + r) * 768 + kb + col];
            sbuf[NT * KC + idx] = twt[(size_t)(n0 + r) * 768 + kb + col];
        }
        __syncthreads();
        if (j < 64) {
            const float* w = (j < 32 ? Wd + (size_t)j * 768
                                     : Wt + (size_t)(j - 32) * 768) + kb;
            const float* s = (j < 32 ? sbuf : sbuf + NT * KC);
            for (int k = 0; k < KC; k += 8) {
                const float4 w0 = *(const float4*)(w + k);
                const float4 w1 = *(const float4*)(w + k + 4);
#pragma unroll
                for (int m = 0; m < NT; m++) {
                    const float4 a0 = *(const float4*)(s + m * KC + k);
                    const float4 a1 = *(const float4*)(s + m * KC + k + 4);
                    acc[m] += a0.x * w0.x + a0.y * w0.y + a0.z * w0.z + a0.w * w0.w;
                    acc[m] += a1.x * w1.x + a1.y * w1.y + a1.z * w1.z + a1.w * w1.w;
                }
            }
        }
        __syncthreads();
    }

    // ---- stage 1 epilogue: write x = concat(d,t,n,c) rows ------------------
    if (j < 32) {
        const float b = bd[j];
#pragma unroll
        for (int m = 0; m < NT; m++) sh[m * 132 + j] = lrelu01(acc[m] + b);
    } else if (j < 64) {
        const float b = bt[j - 32];
#pragma unroll
        for (int m = 0; m < NT; m++) sh[m * 132 + j] = lrelu01(acc[m] + b);
    } else if (j < 96) {
        const int jj = j - 64;
        const float w0 = Wn[jj * 5], w1 = Wn[jj * 5 + 1], w2 = Wn[jj * 5 + 2],
                    w3 = Wn[jj * 5 + 3], w4 = Wn[jj * 5 + 4];
        const float b = bn[jj];
        for (int m = 0; m < NT; m++) {
            const float* r = npr + (size_t)(n0 + m) * 5;
            sh[m * 132 + j] =
                lrelu01(r[0] * w0 + r[1] * w1 + r[2] * w2 + r[3] * w3 + r[4] * w4 + b);
        }
    } else {
        const int jj = j - 96;
        const float w0 = Wc[jj * 3], w1 = Wc[jj * 3 + 1], w2 = Wc[jj * 3 + 2];
        const float b = bc[jj];
        for (int m = 0; m < NT; m++) {
            const float* r = cpr + (size_t)(n0 + m) * 3;
            sh[m * 132 + j] = lrelu01(r[0] * w0 + r[1] * w1 + r[2] * w2 + b);
        }
    }
    __syncthreads();

    // ---- stage 2: x2 = lrelu(x @ Wi^T + bi) --------------------------------
    {
        const float* w = Wi + (size_t)j * HID;
#pragma unroll
        for (int m = 0; m < NT; m++) acc[m] = 0.f;
        for (int k = 0; k < HID; k += 8) {
            const float4 w0 = *(const float4*)(w + k);
            const float4 w1 = *(const float4*)(w + k + 4);
#pragma unroll
            for (int m = 0; m < NT; m++) {
                const float4 a0 = *(const float4*)(sh + m * 132 + k);
                const float4 a1 = *(const float4*)(sh + m * 132 + k + 4);
                acc[m] += a0.x * w0.x + a0.y * w0.y + a0.z * w0.z + a0.w * w0.w;
                acc[m] += a1.x * w1.x + a1.y * w1.y + a1.z * w1.z + a1.w * w1.w;
            }
        }
        const float b = bi[j];
#pragma unroll
        for (int m = 0; m < NT; m++) sbuf[m * 132 + j] = lrelu01(acc[m] + b);
    }
    __syncthreads();

    // ---- stage 3: xw1 = x2 @ g1_W^T ; e_src/e_dst via warp reduce ----------
    {
        const float* w = g1W + (size_t)j * HID;
#pragma unroll
        for (int m = 0; m < NT; m++) acc[m] = 0.f;
        for (int k = 0; k < HID; k += 8) {
            const float4 w0 = *(const float4*)(w + k);
            const float4 w1 = *(const float4*)(w + k + 4);
#pragma unroll
            for (int m = 0; m < NT; m++) {
                const float4 a0 = *(const float4*)(sbuf + m * 132 + k);
                const float4 a1 = *(const float4*)(sbuf + m * 132 + k + 4);
                acc[m] += a0.x * w0.x + a0.y * w0.y + a0.z * w0.z + a0.w * w0.w;
                acc[m] += a1.x * w1.x + a1.y * w1.y + a1.z * w1.z + a1.w * w1.w;
            }
        }
#pragma unroll
        for (int m = 0; m < NT; m++) g_xw1[(size_t)(n0 + m) * HID + j] = acc[m];

        const float aj = g1as[j], dj = g1ad[j];
        const int h = j >> 5, lane = j & 31;   // warp == head for GAT1
#pragma unroll
        for (int m = 0; m < NT; m++) {
            float vs = acc[m] * aj, vd = acc[m] * dj;
#pragma unroll
            for (int o = 16; o > 0; o >>= 1) {
                vs += __shfl_xor_sync(0xffffffffu, vs, o);
                vd += __shfl_xor_sync(0xffffffffu, vd, o);
            }
            if (lane == 0) {
                g_es1[(n0 + m) * 4 + h] = vs;
                g_ed1[(n0 + m) * 4 + h] = vd;
            }
        }
    }
}

// ---------------- GAT1: per-slot exp (no atomics) -----------------------------
__global__ void k_ex1() {
    const int s = blockIdx.x * blockDim.x + threadIdx.x;
    if (s >= ET) return;
    const int src = g_csrc[s], dst = g_cdst[s];
    const float4 es = *(const float4*)(g_es1 + src * 4);
    const float4 ed = *(const float4*)(g_ed1 + dst * 4);
    float4 ex;
    ex.x = expf(lrelu2(es.x + ed.x));
    ex.y = expf(lrelu2(es.y + ed.y));
    ex.z = expf(lrelu2(es.z + ed.z));
    ex.w = expf(lrelu2(es.w + ed.w));
    *(float4*)(g_ex1 + (size_t)s * 4) = ex;
}

// ---------------- GAT1 aggregation: warp-per-dst gather -----------------------
__global__ void __launch_bounds__(256) k_agg1(const float* __restrict__ g1b) {
    const int d = (blockIdx.x * blockDim.x + threadIdx.x) >> 5;
    const int lane = threadIdx.x & 31;
    if (d >= NN) return;
    const int beg = g_rs[d], end = g_rs[d + 1];
    const int h = lane >> 3;                 // head for dims 4*lane..4*lane+3
    float4 acc = {0.f, 0.f, 0.f, 0.f};
    float den = 0.f;
#pragma unroll 2
    for (int s = beg; s < end; s++) {
        const int src = __ldg(&g_csrc[s]);
        const float ev = __ldg(&g_ex1[(size_t)s * 4 + h]);
        const float4 xs = *(const float4*)(g_xw1 + (size_t)src * HID + lane * 4);
        acc.x += xs.x * ev; acc.y += xs.y * ev;
        acc.z += xs.z * ev; acc.w += xs.w * ev;
        den += ev;
    }
    const float inv = 1.f / den;
    const float4 b = ((const float4*)g1b)[lane];
    float4 o;
    o.x = acc.x * inv + b.x; o.y = acc.y * inv + b.y;
    o.z = acc.z * inv + b.z; o.w = acc.w * inv + b.w;
    *(float4*)(g_out1 + (size_t)d * HID + lane * 4) = o;
}

// ---------------- GAT2 projection + attn logits -------------------------------
__global__ void __launch_bounds__(128, 1) k_gat2_prep(
    const float* __restrict__ g2W,
    const float* __restrict__ g2as, const float* __restrict__ g2ad)
{
    __shared__ float sx[NT * 132];
    __shared__ float sp[2][4][NT];
    const int tid = threadIdx.x, n0 = blockIdx.x * NT, j = tid;

    for (int idx = tid; idx < NT * HID; idx += 128) {
        const int m = idx >> 7, c = idx & 127;
        sx[m * 132 + c] = g_out1[(size_t)(n0 + m) * HID + c];   // bias folded in agg1
    }
    __syncthreads();

    float acc[NT];
#pragma unroll
    for (int m = 0; m < NT; m++) acc[m] = 0.f;
    const float* w = g2W + (size_t)j * HID;
    for (int k = 0; k < HID; k += 8) {
        const float4 w0 = *(const float4*)(w + k);
        const float4 w1 = *(const float4*)(w + k + 4);
#pragma unroll
        for (int m = 0; m < NT; m++) {
            const float4 a0 = *(const float4*)(sx + m * 132 + k);
            const float4 a1 = *(const float4*)(sx + m * 132 + k + 4);
            acc[m] += a0.x * w0.x + a0.y * w0.y + a0.z * w0.z + a0.w * w0.w;
            acc[m] += a1.x * w1.x + a1.y * w1.y + a1.z * w1.z + a1.w * w1.w;
        }
    }
#pragma unroll
    for (int m = 0; m < NT; m++) g_xw2[(size_t)(n0 + m) * HID + j] = acc[m];

    const float aj = g2as[j], dj = g2ad[j];
    const int wp = j >> 5, lane = j & 31;
#pragma unroll
    for (int m = 0; m < NT; m++) {
        float vs = acc[m] * aj, vd = acc[m] * dj;
#pragma unroll
        for (int o = 16; o > 0; o >>= 1) {
            vs += __shfl_xor_sync(0xffffffffu, vs, o);
            vd += __shfl_xor_sync(0xffffffffu, vd, o);
        }
        if (lane == 0) { sp[0][wp][m] = vs; sp[1][wp][m] = vd; }
    }
    __syncthreads();
    if (tid < 32) {
        g_es2[n0 + tid] = sp[0][0][tid] + sp[0][1][tid] + sp[0][2][tid] + sp[0][3][tid];
    } else if (tid < 64) {
        const int m = tid - 32;
        g_ed2[n0 + m] = sp[1][0][m] + sp[1][1][m] + sp[1][2][m] + sp[1][3][m];
    }
}

// ---------------- GAT2: per-slot exp + warp gather ----------------------------
__global__ void k_ex2() {
    const int s = blockIdx.x * blockDim.x + threadIdx.x;
    if (s >= ET) return;
    g_ex2[s] = expf(lrelu2(g_es2[g_csrc[s]] + g_ed2[g_cdst[s]]));
}

__global__ void __launch_bounds__(256) k_agg2(const float* __restrict__ g2b) {
    const int d = (blockIdx.x * blockDim.x + threadIdx.x) >> 5;
    const int lane = threadIdx.x & 31;
    if (d >= NN) return;
    const int beg = g_rs[d], end = g_rs[d + 1];
    float4 acc = {0.f, 0.f, 0.f, 0.f};
    float den = 0.f;
#pragma unroll 2
    for (int s = beg; s < end; s++) {
        const int src = __ldg(&g_csrc[s]);
        const float ev = __ldg(&g_ex2[s]);
        const float4 xs = *(const float4*)(g_xw2 + (size_t)src * HID + lane * 4);
        acc.x += xs.x * ev; acc.y += xs.y * ev;
        acc.z += xs.z * ev; acc.w += xs.w * ev;
        den += ev;
    }
    const float inv = 1.f / den;
    const float4 b = ((const float4*)g2b)[lane];
    float4 o;
    o.x = acc.x * inv + b.x; o.y = acc.y * inv + b.y;
    o.z = acc.z * inv + b.z; o.w = acc.w * inv + b.w;
    *(float4*)(g_out2 + (size_t)d * HID + lane * 4) = o;
}

// ---------------- output head ------------------------------------------------
__global__ void __launch_bounds__(128, 1) k_final(
    const float* __restrict__ Wo1,
    const float* __restrict__ bo1, const float* __restrict__ Wo2,
    const float* __restrict__ bo2, float* __restrict__ out)
{
    __shared__ float sx[NT * 132];
    __shared__ float sp[2][4][NT];
    const int tid = threadIdx.x, n0 = blockIdx.x * NT, j = tid;

    for (int idx = tid; idx < NT * HID; idx += 128) {
        const int m = idx >> 7, c = idx & 127;
        sx[m * 132 + c] = g_out2[(size_t)(n0 + m) * HID + c];   // bias folded in agg2
    }
    __syncthreads();

    float acc[NT];
#pragma unroll
    for (int m = 0; m < NT; m++) acc[m] = 0.f;
    const float* w = Wo1 + (size_t)j * HID;
    for (int k = 0; k < HID; k += 8) {
        const float4 w0 = *(const float4*)(w + k);
        const float4 w1 = *(const float4*)(w + k + 4);
#pragma unroll
        for (int m = 0; m < NT; m++) {
            const float4 a0 = *(const float4*)(sx + m * 132 + k);
            const float4 a1 = *(const float4*)(sx + m * 132 + k + 4);
            acc[m] += a0.x * w0.x + a0.y * w0.y + a0.z * w0.z + a0.w * w0.w;
            acc[m] += a1.x * w1.x + a1.y * w1.y + a1.z * w1.z + a1.w * w1.w;
        }
    }
    const float b1 = bo1[j];
    const float w0o = Wo2[j], w1o = Wo2[HID + j];
    const int wp = j >> 5, lane = j & 31;
#pragma unroll
    for (int m = 0; m < NT; m++) {
        const float y = lrelu01(acc[m] + b1);
        float v0 = y * w0o, v1 = y * w1o;
#pragma unroll
        for (int o = 16; o > 0; o >>= 1) {
            v0 += __shfl_xor_sync(0xffffffffu, v0, o);
            v1 += __shfl_xor_sync(0xffffffffu, v1, o);
        }
        if (lane == 0) { sp[0][wp][m] = v0; sp[1][wp][m] = v1; }
    }
    __syncthreads();
    if (tid < 32) {
        out[(size_t)(n0 + tid) * 2] =
            sp[0][0][tid] + sp[0][1][tid] + sp[0][2][tid] + sp[0][3][tid] + bo2[0];
    } else if (tid < 64) {
        const int m = tid - 32;
        out[(size_t)(n0 + m) * 2 + 1] =
            sp[1][0][m] + sp[1][1][m] + sp[1][2][m] + sp[1][3][m] + bo2[1];
    }
}

// ---------------- launch ------------------------------------------------------
extern "C" void kernel_launch(void* const* d_in, const int* in_sizes, int n_in,
                              void* d_out, int out_size) {
    const float* des  = (const float*)d_in[0];
    const float* twt  = (const float*)d_in[1];
    const float* npr  = (const float*)d_in[2];
    const float* cpr  = (const float*)d_in[3];
    const int*   ei   = (const int*)d_in[4];   // JAX x64 disabled -> int32
    const float* Wd = (const float*)d_in[5];   const float* bd = (const float*)d_in[6];
    const float* Wt = (const float*)d_in[7];   const float* bt = (const float*)d_in[8];
    const float* Wn = (const float*)d_in[9];   const float* bn = (const float*)d_in[10];
    const float* Wc = (const float*)d_in[11];  const float* bc = (const float*)d_in[12];
    const float* Wi = (const float*)d_in[13];  const float* bi = (const float*)d_in[14];
    const float* g1W  = (const float*)d_in[15];
    const float* g1as = (const float*)d_in[16];
    const float* g1ad = (const float*)d_in[17];
    const float* g1b  = (const float*)d_in[18];
    const float* g2W  = (const float*)d_in[19];
    const float* g2as = (const float*)d_in[20];
    const float* g2ad = (const float*)d_in[21];
    const float* g2b  = (const float*)d_in[22];
    const float* Wo1  = (const float*)d_in[23]; const float* bo1 = (const float*)d_in[24];
    const float* Wo2  = (const float*)d_in[25]; const float* bo2 = (const float*)d_in[26];
    float* out = (float*)d_out;

    // CSR build (int atomics only)
    k_init_cnt<<<(NN + 255) / 256, 256>>>();
    k_count<<<(EE + 255) / 256, 256>>>(ei);
    k_scan<<<1, 1024>>>();
    k_fill<<<(ET + 255) / 256, 256>>>(ei);

    // network
    k_features<<<NN / NT, 128>>>(des, twt, npr, cpr, Wd, bd, Wt, bt, Wn, bn,
                                 Wc, bc, Wi, bi, g1W, g1as, g1ad);
    k_ex1<<<(ET + 255) / 256, 256>>>();
    k_agg1<<<(NN * 32 + 255) / 256, 256>>>(g1b);
    k_gat2_prep<<<NN / NT, 128>>>(g2W, g2as, g2ad);
    k_ex2<<<(ET + 255) / 256, 256>>>();
    k_agg2<<<(NN * 32 + 255) / 256, 256>>>(g2b);
    k_final<<<NN / NT, 128>>>(Wo1, bo1, Wo2, bo2, out);
}

// round 4
// speedup vs baseline: 1.4870x; 1.0843x over previous
#include <cuda_runtime.h>

#define NN   100000
#define EE   1600000
#define ET   (EE + NN)          // edges + self loops = 1,700,000
#define HID  128
#define NT   32                 // nodes per block in per-node kernels
#define TS   36                 // transposed smem row stride (floats)

// ---------------- scratch (device globals: no allocation allowed) -------------
__device__ __align__(16) float g_xw1 [(size_t)NN * HID];
__device__ __align__(16) float g_es1 [NN * 4];
__device__ __align__(16) float g_ed1 [NN * 4];
__device__ __align__(16) float g_out1[(size_t)NN * HID];
__device__ __align__(16) float g_xw2 [(size_t)NN * HID];
__device__ __align__(16) float g_es2 [NN];
__device__ __align__(16) float g_ed2 [NN];
__device__ __align__(16) float g_out2[(size_t)NN * HID];

// CSR (dst-grouped), rebuilt every launch (graph-capture safe, no allocs)
__device__ int g_cnt[NN];
__device__ int g_rs [NN + 1];
__device__ int g_cur[NN];
__device__ int g_csrc[ET];

__device__ __forceinline__ float lrelu01(float v) { return v > 0.f ? v : 0.01f * v; }
__device__ __forceinline__ float lrelu2 (float v) { return v > 0.f ? v : 0.2f  * v; }

// ---- packed fp32x2 helpers ---------------------------------------------------
__device__ __forceinline__ unsigned long long pack2(float x, float y) {
    unsigned long long r;
    asm("mov.b64 %0,{%1,%2};" : "=l"(r) : "f"(x), "f"(y));
    return r;
}
__device__ __forceinline__ float2 unpack2(unsigned long long v) {
    float2 r;
    asm("mov.b64 {%0,%1},%2;" : "=f"(r.x), "=f"(r.y) : "l"(v));
    return r;
}
__device__ __forceinline__ void ffma2(unsigned long long& d,
                                      unsigned long long a, unsigned long long b) {
    asm("fma.rn.f32x2 %0,%1,%2,%0;" : "+l"(d) : "l"(a), "l"(b));
}

// K-step over transposed activation tile: acc2[16] covers 32 nodes (16 pairs)
__device__ __forceinline__ void gemm_kstep(const float* __restrict__ arow,
                                           unsigned long long wp,
                                           unsigned long long* acc2) {
#pragma unroll
    for (int q = 0; q < 8; q++) {
        const ulonglong2 av = *(const ulonglong2*)(arow + 4 * q);
        ffma2(acc2[2 * q],     av.x, wp);
        ffma2(acc2[2 * q + 1], av.y, wp);
    }
}

template <int KLEN>
__device__ __forceinline__ void gemm_col(const float* __restrict__ w,
                                         const float* __restrict__ a_t,
                                         unsigned long long* acc2) {
#pragma unroll 4
    for (int k = 0; k < KLEN; k += 4) {
        const float4 wv = *(const float4*)(w + k);
        gemm_kstep(a_t + (k + 0) * TS, pack2(wv.x, wv.x), acc2);
        gemm_kstep(a_t + (k + 1) * TS, pack2(wv.y, wv.y), acc2);
        gemm_kstep(a_t + (k + 2) * TS, pack2(wv.z, wv.z), acc2);
        gemm_kstep(a_t + (k + 3) * TS, pack2(wv.w, wv.w), acc2);
    }
}

// ---------------- CSR build ---------------------------------------------------
__global__ void k_init_cnt() {
    int i = blockIdx.x * blockDim.x + threadIdx.x;
    if (i < NN) g_cnt[i] = 1;            // self loop pre-counted
}

__global__ void k_count(const int* __restrict__ ei) {
    int i = blockIdx.x * blockDim.x + threadIdx.x;
    if (i < EE) atomicAdd(&g_cnt[ei[EE + i]], 1);
}

__global__ void __launch_bounds__(1024, 1) k_scan() {  // single block
    __shared__ int ssum[1024];
    const int t = threadIdx.x;
    const int C = (NN + 1023) / 1024;
    const int beg = t * C;
    const int end = (beg + C < NN) ? beg + C : NN;
    int s = 0;
    for (int i = beg; i < end; i++) s += g_cnt[i];
    ssum[t] = s;
    __syncthreads();
    for (int o = 1; o < 1024; o <<= 1) {
        int v = (t >= o) ? ssum[t - o] : 0;
        __syncthreads();
        ssum[t] += v;
        __syncthreads();
    }
    int pre = (t == 0) ? 0 : ssum[t - 1];
    for (int i = beg; i < end; i++) {
        g_rs[i] = pre;
        g_cur[i] = pre;
        pre += g_cnt[i];
    }
    if (t == 0) g_rs[NN] = ET;
}

__global__ void k_fill(const int* __restrict__ ei) {
    int i = blockIdx.x * blockDim.x + threadIdx.x;
    if (i >= ET) return;
    int src, dst;
    if (i < EE) { src = ei[i]; dst = ei[EE + i]; }
    else        { src = dst = i - EE; }
    const int slot = atomicAdd(&g_cur[dst], 1);
    g_csrc[slot] = src;
}

// ---------------- features -> x -> Wi -> g1 projection + attn logits ---------
__global__ void __launch_bounds__(128) k_features(
    const float* __restrict__ des, const float* __restrict__ twt,
    const float* __restrict__ npr, const float* __restrict__ cpr,
    const float* __restrict__ Wd, const float* __restrict__ bd,
    const float* __restrict__ Wt, const float* __restrict__ bt,
    const float* __restrict__ Wn, const float* __restrict__ bn,
    const float* __restrict__ Wc, const float* __restrict__ bc,
    const float* __restrict__ Wi, const float* __restrict__ bi,
    const float* __restrict__ g1W, const float* __restrict__ g1as,
    const float* __restrict__ g1ad)
{
    __shared__ __align__(16) float sh_t[128 * TS];     // x transposed [feat][node]
    __shared__ __align__(16) float sbuf[2 * 96 * TS];  // stage1 tiles / red / x2_t

    const int tid  = threadIdx.x;
    const int n0   = blockIdx.x * NT;
    const int j    = tid & 63;          // stage-1 column
    const int half = tid >> 6;          // stage-1 K half

    unsigned long long acc2[16];
#pragma unroll
    for (int p = 0; p < 16; p++) acc2[p] = 0ull;

    // ---- stage 1: d/t columns, 8 chunks of K=96, split across thread halves --
    {
        const float* wrow  = (j < 32) ? Wd + (size_t)j * 768
                                      : Wt + (size_t)(j - 32) * 768;
        const float* sbase = (j < 32) ? sbuf : sbuf + 96 * TS;

        for (int c = 0; c < 8; c++) {
            const int kb = c * 96;
            for (int idx = tid; idx < 32 * 96; idx += 128) {
                const int r = idx / 96, col = idx - r * 96;
                sbuf[col * TS + r]           = des[(size_t)(n0 + r) * 768 + kb + col];
                sbuf[96 * TS + col * TS + r] = twt[(size_t)(n0 + r) * 768 + kb + col];
            }
            __syncthreads();
            if ((c >> 2) == half) {
                gemm_col<96>(wrow + kb, sbase, acc2);
            }
            __syncthreads();
        }
    }

    // ---- stage 1 epilogue: cross-half reduce + num/cat columns ---------------
    {
        float* red = sbuf;   // 64 cols x 32 nodes
        if (half == 1) {
#pragma unroll
            for (int p = 0; p < 16; p++)
                *(unsigned long long*)(red + j * 32 + 2 * p) = acc2[p];
        }
        __syncthreads();
        if (half == 0) {
            const float b = (j < 32) ? bd[j] : bt[j - 32];
#pragma unroll
            for (int p = 0; p < 16; p++) {
                const float2 o  = unpack2(acc2[p]);
                const float2 r2 = *(const float2*)(red + j * 32 + 2 * p);
                sh_t[j * TS + 2 * p]     = lrelu01(o.x + r2.x + b);
                sh_t[j * TS + 2 * p + 1] = lrelu01(o.y + r2.y + b);
            }
        } else if (j < 32) {     // num_prop -> column 64+j
            const float w0 = Wn[j * 5], w1 = Wn[j * 5 + 1], w2 = Wn[j * 5 + 2],
                        w3 = Wn[j * 5 + 3], w4 = Wn[j * 5 + 4];
            const float b = bn[j];
            for (int m = 0; m < NT; m++) {
                const float* r = npr + (size_t)(n0 + m) * 5;
                sh_t[(64 + j) * TS + m] =
                    lrelu01(r[0]*w0 + r[1]*w1 + r[2]*w2 + r[3]*w3 + r[4]*w4 + b);
            }
        } else {                 // cat_prop -> column 96+(j-32)
            const int jj = j - 32;
            const float w0 = Wc[jj * 3], w1 = Wc[jj * 3 + 1], w2 = Wc[jj * 3 + 2];
            const float b = bc[jj];
            for (int m = 0; m < NT; m++) {
                const float* r = cpr + (size_t)(n0 + m) * 3;
                sh_t[(96 + jj) * TS + m] = lrelu01(r[0]*w0 + r[1]*w1 + r[2]*w2 + b);
            }
        }
    }
    __syncthreads();

    // ---- stage 2: x2 = lrelu(x @ Wi^T + bi), column = tid -------------------
    {
#pragma unroll
        for (int p = 0; p < 16; p++) acc2[p] = 0ull;
        gemm_col<128>(Wi + (size_t)tid * HID, sh_t, acc2);
        const float b = bi[tid];
        float* x2_t = sbuf;   // 128 x TS fits
#pragma unroll
        for (int p = 0; p < 16; p++) {
            const float2 o = unpack2(acc2[p]);
            x2_t[tid * TS + 2 * p]     = lrelu01(o.x + b);
            x2_t[tid * TS + 2 * p + 1] = lrelu01(o.y + b);
        }
    }
    __syncthreads();

    // ---- stage 3: xw1 = x2 @ g1_W^T ; per-head logits -----------------------
    {
#pragma unroll
        for (int p = 0; p < 16; p++) acc2[p] = 0ull;
        gemm_col<128>(g1W + (size_t)tid * HID, sbuf, acc2);

        float vals[NT];
#pragma unroll
        for (int p = 0; p < 16; p++) {
            const float2 o = unpack2(acc2[p]);
            vals[2 * p] = o.x; vals[2 * p + 1] = o.y;
        }
#pragma unroll
        for (int m = 0; m < NT; m++)
            g_xw1[(size_t)(n0 + m) * HID + tid] = vals[m];

        const float aj = g1as[tid], dj = g1ad[tid];
        const int h = tid >> 5, lane = tid & 31;    // warp == head
#pragma unroll
        for (int m = 0; m < NT; m++) {
            float vs = vals[m] * aj, vd = vals[m] * dj;
#pragma unroll
            for (int o = 16; o > 0; o >>= 1) {
                vs += __shfl_xor_sync(0xffffffffu, vs, o);
                vd += __shfl_xor_sync(0xffffffffu, vd, o);
            }
            if (lane == 0) {
                g_es1[(n0 + m) * 4 + h] = vs;
                g_ed1[(n0 + m) * 4 + h] = vd;
            }
        }
    }
}

// ---------------- GAT1 aggregation: warp-per-dst gather, fused exp ------------
__global__ void __launch_bounds__(256) k_agg1(const float* __restrict__ g1b) {
    const int d = (blockIdx.x * blockDim.x + threadIdx.x) >> 5;
    const int lane = threadIdx.x & 31;
    if (d >= NN) return;
    const int beg = g_rs[d], end = g_rs[d + 1];
    const int h = lane >> 3;                 // head for dims 4*lane..4*lane+3
    const float edv = g_ed1[d * 4 + h];
    float4 acc = {0.f, 0.f, 0.f, 0.f};
    float den = 0.f;
#pragma unroll 2
    for (int s = beg; s < end; s++) {
        const int src = __ldg(&g_csrc[s]);
        const float es = __ldg(&g_es1[src * 4 + h]);
        const float ev = __expf(lrelu2(es + edv));
        const float4 xs = *(const float4*)(g_xw1 + (size_t)src * HID + lane * 4);
        acc.x += xs.x * ev; acc.y += xs.y * ev;
        acc.z += xs.z * ev; acc.w += xs.w * ev;
        den += ev;
    }
    const float inv = 1.f / den;
    const float4 b = ((const float4*)g1b)[lane];
    float4 o;
    o.x = acc.x * inv + b.x; o.y = acc.y * inv + b.y;
    o.z = acc.z * inv + b.z; o.w = acc.w * inv + b.w;
    *(float4*)(g_out1 + (size_t)d * HID + lane * 4) = o;
}

// ---------------- GAT2 projection + attn logits -------------------------------
__global__ void __launch_bounds__(128) k_gat2_prep(
    const float* __restrict__ g2W,
    const float* __restrict__ g2as, const float* __restrict__ g2ad)
{
    __shared__ __align__(16) float sx_t[128 * TS];
    __shared__ float sp[2][4][NT];
    const int tid = threadIdx.x, n0 = blockIdx.x * NT;

    for (int idx = tid; idx < NT * HID; idx += 128) {
        const int m = idx >> 7, c = idx & 127;
        sx_t[c * TS + m] = g_out1[(size_t)(n0 + m) * HID + c];
    }
    __syncthreads();

    unsigned long long acc2[16];
#pragma unroll
    for (int p = 0; p < 16; p++) acc2[p] = 0ull;
    gemm_col<128>(g2W + (size_t)tid * HID, sx_t, acc2);

    float vals[NT];
#pragma unroll
    for (int p = 0; p < 16; p++) {
        const float2 o = unpack2(acc2[p]);
        vals[2 * p] = o.x; vals[2 * p + 1] = o.y;
    }
#pragma unroll
    for (int m = 0; m < NT; m++)
        g_xw2[(size_t)(n0 + m) * HID + tid] = vals[m];

    const float aj = g2as[tid], dj = g2ad[tid];
    const int wp = tid >> 5, lane = tid & 31;
#pragma unroll
    for (int m = 0; m < NT; m++) {
        float vs = vals[m] * aj, vd = vals[m] * dj;
#pragma unroll
        for (int o = 16; o > 0; o >>= 1) {
            vs += __shfl_xor_sync(0xffffffffu, vs, o);
            vd += __shfl_xor_sync(0xffffffffu, vd, o);
        }
        if (lane == 0) { sp[0][wp][m] = vs; sp[1][wp][m] = vd; }
    }
    __syncthreads();
    if (tid < 32) {
        g_es2[n0 + tid] = sp[0][0][tid] + sp[0][1][tid] + sp[0][2][tid] + sp[0][3][tid];
    } else if (tid < 64) {
        const int m = tid - 32;
        g_ed2[n0 + m] = sp[1][0][m] + sp[1][1][m] + sp[1][2][m] + sp[1][3][m];
    }
}

// ---------------- GAT2 aggregation: fused exp ---------------------------------
__global__ void __launch_bounds__(256) k_agg2(const float* __restrict__ g2b) {
    const int d = (blockIdx.x * blockDim.x + threadIdx.x) >> 5;
    const int lane = threadIdx.x & 31;
    if (d >= NN) return;
    const int beg = g_rs[d], end = g_rs[d + 1];
    const float edv = g_ed2[d];
    float4 acc = {0.f, 0.f, 0.f, 0.f};
    float den = 0.f;
#pragma unroll 2
    for (int s = beg; s < end; s++) {
        const int src = __ldg(&g_csrc[s]);
        const float es = __ldg(&g_es2[src]);
        const float ev = __expf(lrelu2(es + edv));
        const float4 xs = *(const float4*)(g_xw2 + (size_t)src * HID + lane * 4);
        acc.x += xs.x * ev; acc.y += xs.y * ev;
        acc.z += xs.z * ev; acc.w += xs.w * ev;
        den += ev;
    }
    const float inv = 1.f / den;
    const float4 b = ((const float4*)g2b)[lane];
    float4 o;
    o.x = acc.x * inv + b.x; o.y = acc.y * inv + b.y;
    o.z = acc.z * inv + b.z; o.w = acc.w * inv + b.w;
    *(float4*)(g_out2 + (size_t)d * HID + lane * 4) = o;
}

// ---------------- output head ------------------------------------------------
__global__ void __launch_bounds__(128) k_final(
    const float* __restrict__ Wo1,
    const float* __restrict__ bo1, const float* __restrict__ Wo2,
    const float* __restrict__ bo2, float* __restrict__ out)
{
    __shared__ __align__(16) float sx_t[128 * TS];
    __shared__ float sp[2][4][NT];
    const int tid = threadIdx.x, n0 = blockIdx.x * NT;

    for (int idx = tid; idx < NT * HID; idx += 128) {
        const int m = idx >> 7, c = idx & 127;
        sx_t[c * TS + m] = g_out2[(size_t)(n0 + m) * HID + c];
    }
    __syncthreads();

    unsigned long long acc2[16];
#pragma unroll
    for (int p = 0; p < 16; p++) acc2[p] = 0ull;
    gemm_col<128>(Wo1 + (size_t)tid * HID, sx_t, acc2);

    const float b1 = bo1[tid];
    const float w0o = Wo2[tid], w1o = Wo2[HID + tid];
    const int wp = tid >> 5, lane = tid & 31;
    float vals[NT];
#pragma unroll
    for (int p = 0; p < 16; p++) {
        const float2 o = unpack2(acc2[p]);
        vals[2 * p]     = lrelu01(o.x + b1);
        vals[2 * p + 1] = lrelu01(o.y + b1);
    }
#pragma unroll
    for (int m = 0; m < NT; m++) {
        float v0 = vals[m] * w0o, v1 = vals[m] * w1o;
#pragma unroll
        for (int o = 16; o > 0; o >>= 1) {
            v0 += __shfl_xor_sync(0xffffffffu, v0, o);
            v1 += __shfl_xor_sync(0xffffffffu, v1, o);
        }
        if (lane == 0) { sp[0][wp][m] = v0; sp[1][wp][m] = v1; }
    }
    __syncthreads();
    if (tid < 32) {
        out[(size_t)(n0 + tid) * 2] =
            sp[0][0][tid] + sp[0][1][tid] + sp[0][2][tid] + sp[0][3][tid] + bo2[0];
    } else if (tid < 64) {
        const int m = tid - 32;
        out[(size_t)(n0 + m) * 2 + 1] =
            sp[1][0][m] + sp[1][1][m] + sp[1][2][m] + sp[1][3][m] + bo2[1];
    }
}

// ---------------- launch ------------------------------------------------------
extern "C" void kernel_launch(void* const* d_in, const int* in_sizes, int n_in,
                              void* d_out, int out_size) {
    const float* des  = (const float*)d_in[0];
    const float* twt  = (const float*)d_in[1];
    const float* npr  = (const float*)d_in[2];
    const float* cpr  = (const float*)d_in[3];
    const int*   ei   = (const int*)d_in[4];   // JAX x64 disabled -> int32
    const float* Wd = (const float*)d_in[5];   const float* bd = (const float*)d_in[6];
    const float* Wt = (const float*)d_in[7];   const float* bt = (const float*)d_in[8];
    const float* Wn = (const float*)d_in[9];   const float* bn = (const float*)d_in[10];
    const float* Wc = (const float*)d_in[11];  const float* bc = (const float*)d_in[12];
    const float* Wi = (const float*)d_in[13];  const float* bi = (const float*)d_in[14];
    const float* g1W  = (const float*)d_in[15];
    const float* g1as = (const float*)d_in[16];
    const float* g1ad = (const float*)d_in[17];
    const float* g1b  = (const float*)d_in[18];
    const float* g2W  = (const float*)d_in[19];
    const float* g2as = (const float*)d_in[20];
    const float* g2ad = (const float*)d_in[21];
    const float* g2b  = (const float*)d_in[22];
    const float* Wo1  = (const float*)d_in[23]; const float* bo1 = (const float*)d_in[24];
    const float* Wo2  = (const float*)d_in[25]; const float* bo2 = (const float*)d_in[26];
    float* out = (float*)d_out;

    // CSR build (int atomics only)
    k_init_cnt<<<(NN + 255) / 256, 256>>>();
    k_count<<<(EE + 255) / 256, 256>>>(ei);
    k_scan<<<1, 1024>>>();
    k_fill<<<(ET + 255) / 256, 256>>>(ei);

    // network
    k_features<<<NN / NT, 128>>>(des, twt, npr, cpr, Wd, bd, Wt, bt, Wn, bn,
                                 Wc, bc, Wi, bi, g1W, g1as, g1ad);
    k_agg1<<<(NN * 32 + 255) / 256, 256>>>(g1b);
    k_gat2_prep<<<NN / NT, 128>>>(g2W, g2as, g2ad);
    k_agg2<<<(NN * 32 + 255) / 256, 256>>>(g2b);
    k_final<<<NN / NT, 128>>>(Wo1, bo1, Wo2, bo2, out);
}